// round 12
// baseline (speedup 1.0000x reference)
#include <cuda_runtime.h>
#include <cuda_bf16.h>
#include <mma.h>
using namespace nvcuda;

#define NN   100000
#define NNP  100096   // padded to 128-node tiles: 782*128
#define NE   1600000
#define INF_ 128
#define OUTF 64
#define TILE_M 128
#define NBLK ((NN + TILE_M - 1) / TILE_M)   // 782
#define CAP  64
#define MAX_OVF 65536
#define EPB  ((NE + NBLK - 1) / NBLK)       // edges per gemm block (2046)

__device__ float g_support[(size_t)NNP * OUTF];
__device__ float g_resid[(size_t)NNP * OUTF];
__device__ __align__(16) __nv_bfloat16 g_whi[128 * 128];
__device__ __align__(16) __nv_bfloat16 g_wlo[128 * 128];
__device__ int  g_cnt[NNP + 1];             // [NNP] = overflow counter
__device__ int  g_ovf[MAX_OVF];
__device__ int2 g_ell[(size_t)NNP * CAP];   // {src*16 (float4 units), w bits}

// ---------------------------------------------------------------------------
// Prep: split combined weight matrix into bf16 hi/lo. [k][f], f>=64 -> res_w^T
// ---------------------------------------------------------------------------
__global__ void prep_weights(const float* __restrict__ w,
                             const float* __restrict__ rw) {
  int i = blockIdx.x * blockDim.x + threadIdx.x;
  if (i >= 128 * 128) return;
  int k = i >> 7, f = i & 127;
  float v = (f < 64) ? w[k * 64 + f] : rw[(f - 64) * 128 + k];
  __nv_bfloat16 h = __float2bfloat16(v);
  g_whi[i] = h;
  g_wlo[i] = __float2bfloat16(v - __bfloat162float(h));
}

// ---------------------------------------------------------------------------
// Kernel 1: WMMA split-bf16 combined GEMM (support | resid) + ELL placement
// slice appended per block (placement overlaps other blocks' tensor work).
// 128 nodes/block, 512 threads = 16 warps (4 m-tiles x 4 n-tiles),
// each warp 2x2 fragments of 16x16, 3 passes (hh, hl, lh), K=128.
// ---------------------------------------------------------------------------
#define LDX 136
#define LDW 136
#define SM_XHI 0
#define SM_XLO (128 * LDX)
#define SM_WHI (2 * 128 * LDX)
#define SM_WLO (2 * 128 * LDX + 128 * LDW)
#define GEMM_SMEM ((2 * 128 * LDX + 2 * 128 * LDW) * 2)   // 139264 B

__global__ void __launch_bounds__(512) gemm_place_kernel(
    const float* __restrict__ x,
    const int* __restrict__ src, const int* __restrict__ dst,
    const float* __restrict__ ew) {
  extern __shared__ __nv_bfloat16 sm[];
  __nv_bfloat16* xhi = sm + SM_XHI;
  __nv_bfloat16* xlo = sm + SM_XLO;
  __nv_bfloat16* whi = sm + SM_WHI;
  __nv_bfloat16* wlo = sm + SM_WLO;
  const int tid = threadIdx.x;
  const int n0 = blockIdx.x * TILE_M;

  // Stage pre-split weights (2048 uint4 per array)
  {
    const uint4* sh = (const uint4*)g_whi;
    const uint4* sl = (const uint4*)g_wlo;
#pragma unroll
    for (int rep = 0; rep < 4; rep++) {
      int i = tid + rep * 512;
      int r = i >> 4, c = i & 15;
      *(uint4*)(whi + r * LDW + c * 8) = sh[i];
      *(uint4*)(wlo + r * LDW + c * 8) = sl[i];
    }
  }
  // Stage x (128 nodes x 32 float4), split hi/lo on the fly
#pragma unroll
  for (int rep = 0; rep < 8; rep++) {
    int i = tid + rep * 512;                 // 4096 float4
    int node = i >> 5, c = i & 31;
    int gn = n0 + node;
    if (gn >= NN) gn = NN - 1;
    float4 v = *(const float4*)(x + (size_t)gn * INF_ + c * 4);
    __nv_bfloat16 h0 = __float2bfloat16(v.x), h1 = __float2bfloat16(v.y);
    __nv_bfloat16 h2 = __float2bfloat16(v.z), h3 = __float2bfloat16(v.w);
    __nv_bfloat16 l0 = __float2bfloat16(v.x - __bfloat162float(h0));
    __nv_bfloat16 l1 = __float2bfloat16(v.y - __bfloat162float(h1));
    __nv_bfloat16 l2 = __float2bfloat16(v.z - __bfloat162float(h2));
    __nv_bfloat16 l3 = __float2bfloat16(v.w - __bfloat162float(h3));
    __nv_bfloat162* ph = (__nv_bfloat162*)(xhi + node * LDX + c * 4);
    __nv_bfloat162* pl = (__nv_bfloat162*)(xlo + node * LDX + c * 4);
    ph[0] = __nv_bfloat162(h0, h1); ph[1] = __nv_bfloat162(h2, h3);
    pl[0] = __nv_bfloat162(l0, l1); pl[1] = __nv_bfloat162(l2, l3);
  }
  __syncthreads();

  const int wid = tid >> 5;
  const int wm = wid & 3;       // node 32-tile (0..3)
  const int wn = wid >> 2;      // feature 32-tile (0..3)

  wmma::fragment<wmma::accumulator, 16, 16, 16, float> acc[2][2];
#pragma unroll
  for (int i = 0; i < 2; i++)
#pragma unroll
    for (int j = 0; j < 2; j++) wmma::fill_fragment(acc[i][j], 0.f);

#pragma unroll
  for (int k = 0; k < 128; k += 16) {
    wmma::fragment<wmma::matrix_a, 16, 16, 16, __nv_bfloat16, wmma::row_major> ahi[2], alo[2];
    wmma::fragment<wmma::matrix_b, 16, 16, 16, __nv_bfloat16, wmma::row_major> bhi[2], blo[2];
#pragma unroll
    for (int i = 0; i < 2; i++) {
      wmma::load_matrix_sync(ahi[i], xhi + (wm * 32 + i * 16) * LDX + k, LDX);
      wmma::load_matrix_sync(alo[i], xlo + (wm * 32 + i * 16) * LDX + k, LDX);
    }
#pragma unroll
    for (int j = 0; j < 2; j++) {
      wmma::load_matrix_sync(bhi[j], whi + k * LDW + wn * 32 + j * 16, LDW);
      wmma::load_matrix_sync(blo[j], wlo + k * LDW + wn * 32 + j * 16, LDW);
    }
#pragma unroll
    for (int i = 0; i < 2; i++)
#pragma unroll
      for (int j = 0; j < 2; j++) {
        wmma::mma_sync(acc[i][j], ahi[i], bhi[j], acc[i][j]);
        wmma::mma_sync(acc[i][j], ahi[i], blo[j], acc[i][j]);
        wmma::mma_sync(acc[i][j], alo[i], bhi[j], acc[i][j]);
      }
  }

#pragma unroll
  for (int i = 0; i < 2; i++)
#pragma unroll
    for (int j = 0; j < 2; j++) {
      int row = n0 + wm * 32 + i * 16;       // < NNP (padded)
      int col = wn * 32 + j * 16;
      float* dstp = (col < 64)
                        ? (g_support + (size_t)row * OUTF + col)
                        : (g_resid + (size_t)row * OUTF + (col - 64));
      wmma::store_matrix_sync(dstp, acc[i][j], OUTF, wmma::mem_row_major);
    }

  // ---- appended ELL placement slice (independent of the GEMM above) ----
  {
    int e0 = blockIdx.x * EPB;
    int e1 = e0 + EPB;
    if (e1 > NE) e1 = NE;
    for (int e = e0 + tid; e < e1; e += 512) {
      int d = __ldg(dst + e);
      int s = __ldg(src + e);
      float w = __ldg(ew + e);
      int pos = atomicAdd(&g_cnt[d], 1);
      if (pos < CAP) {
        g_ell[(size_t)d * CAP + pos] =
            make_int2(s * (OUTF / 4), __float_as_int(w));
      } else {
        int o = atomicAdd(&g_cnt[NNP], 1);
        if (o < MAX_OVF) g_ovf[o] = e;
      }
    }
  }
}

// ---------------------------------------------------------------------------
// Kernel 2: fused gather + finalize. 16 lanes/node (2 nodes per warp).
// Broadcast-LDG ELL entries, MLP=8 gathers, 32-bit address math.
// Padding entries carry w=0 bits -> no per-FMA predicate needed.
// Overflow nodes (deg>CAP) additionally scan the tiny g_ovf list.
// ---------------------------------------------------------------------------
__global__ void __launch_bounds__(256) gather_finalize(
    float* __restrict__ out, const float* __restrict__ bias,
    const float* __restrict__ gamma, const float* __restrict__ beta,
    const float* __restrict__ res_b,
    const int* __restrict__ src, const int* __restrict__ dst,
    const float* __restrict__ ew) {
  unsigned t = blockIdx.x * 256u + threadIdx.x;
  unsigned n = t >> 4;
  unsigned q = t & 15;
  const unsigned gmask = 0xffffu << (threadIdx.x & 16);

  int deg_raw = g_cnt[n];
  int deg = deg_raw > CAP ? CAP : deg_raw;

  float4 acc = make_float4(0.f, 0.f, 0.f, 0.f);
  const int2* ellrow = g_ell + (size_t)n * CAP;
  const float4* supf4 = (const float4*)g_support;

  for (int base = 0; base < deg; base += 8) {
    int2 e[8];
#pragma unroll
    for (int u = 0; u < 8; u++) {
      int idx = base + u;
      e[u] = (idx < deg) ? __ldg(ellrow + idx) : make_int2(0, 0);
    }
    float4 v[8];
#pragma unroll
    for (int u = 0; u < 8; u++)
      v[u] = __ldg(supf4 + (unsigned)(e[u].x + q));
#pragma unroll
    for (int u = 0; u < 8; u++) {
      float w = __int_as_float(e[u].y);    // 0 for padded entries
      acc.x = fmaf(w, v[u].x, acc.x);
      acc.y = fmaf(w, v[u].y, acc.y);
      acc.z = fmaf(w, v[u].z, acc.z);
      acc.w = fmaf(w, v[u].w, acc.w);
    }
  }

  if (deg_raw > CAP) {          // essentially never taken
    int m = g_cnt[NNP];
    if (m > MAX_OVF) m = MAX_OVF;
    for (int i = 0; i < m; i++) {
      int e = g_ovf[i];
      if ((unsigned)__ldg(dst + e) == n) {
        float w = __ldg(ew + e);
        float4 v = __ldg(supf4 + (unsigned)(__ldg(src + e) * (OUTF / 4) + q));
        acc.x = fmaf(w, v.x, acc.x); acc.y = fmaf(w, v.y, acc.y);
        acc.z = fmaf(w, v.z, acc.z); acc.w = fmaf(w, v.w, acc.w);
      }
    }
  }

  // finalize
  float4 b = *(const float4*)(bias + q * 4);
  acc.x += b.x; acc.y += b.y; acc.z += b.z; acc.w += b.w;

  float s  = acc.x + acc.y + acc.z + acc.w;
  float s2 = acc.x * acc.x + acc.y * acc.y + acc.z * acc.z + acc.w * acc.w;
#pragma unroll
  for (int m = 8; m >= 1; m >>= 1) {
    s  += __shfl_xor_sync(gmask, s, m, 16);
    s2 += __shfl_xor_sync(gmask, s2, m, 16);
  }
  float mu  = s * (1.f / 64.f);
  float var = s2 * (1.f / 64.f) - mu * mu;
  float inv = rsqrtf(var + 1e-5f);

  float4 g  = *(const float4*)(gamma + q * 4);
  float4 be = *(const float4*)(beta + q * 4);
  float4 r  = *(const float4*)(g_resid + (size_t)n * OUTF + q * 4);
  float4 rb = *(const float4*)(res_b + q * 4);

  acc.x = fmaxf((acc.x - mu) * inv * g.x + be.x, 0.f) + r.x + rb.x;
  acc.y = fmaxf((acc.y - mu) * inv * g.y + be.y, 0.f) + r.y + rb.y;
  acc.z = fmaxf((acc.z - mu) * inv * g.z + be.z, 0.f) + r.z + rb.z;
  acc.w = fmaxf((acc.w - mu) * inv * g.w + be.w, 0.f) + r.w + rb.w;

  *(float4*)(out + (size_t)n * OUTF + q * 4) = acc;
}

// ---------------------------------------------------------------------------
extern "C" void kernel_launch(void* const* d_in, const int* in_sizes, int n_in,
                              void* d_out, int out_size) {
  const float* x      = (const float*)d_in[0];
  const float* weight = (const float*)d_in[1];
  const float* bias   = (const float*)d_in[2];
  const float* gamma  = (const float*)d_in[3];
  const float* beta   = (const float*)d_in[4];
  const float* res_w  = (const float*)d_in[5];
  const float* res_b  = (const float*)d_in[6];
  const float* ew     = (const float*)d_in[7];
  const int*   esrc   = (const int*)d_in[8];
  const int*   edst   = (const int*)d_in[9];
  float* out = (float*)d_out;

  cudaFuncSetAttribute(gemm_place_kernel,
                       cudaFuncAttributeMaxDynamicSharedMemorySize, GEMM_SMEM);

  void* cntp = nullptr;
  cudaGetSymbolAddress(&cntp, g_cnt);
  cudaMemsetAsync(cntp, 0, (NNP + 1) * sizeof(int), 0);

  prep_weights<<<64, 256>>>(weight, res_w);

  gemm_place_kernel<<<NBLK, 512, GEMM_SMEM>>>(x, esrc, edst, ew);

  gather_finalize<<<(NN * 16) / 256, 256>>>(out, bias, gamma, beta, res_b,
                                            esrc, edst, ew);
}

// round 13
// speedup vs baseline: 1.0847x; 1.0847x over previous
#include <cuda_runtime.h>
#include <cuda_bf16.h>
#include <mma.h>
using namespace nvcuda;

#define NN   100000
#define NNP  100096   // padded to 128-node tiles: 782*128
#define NE   1600000
#define INF_ 128
#define OUTF 64
#define TILE_M 128
#define NBLK ((NN + TILE_M - 1) / TILE_M)   // 782
#define CAP  64
#define MAX_OVF 65536
#define PBLK ((NE / 2 + 255) / 256)         // placement blocks (2 edges/thread)
#define WBLK 64                             // weight-prep blocks

__device__ float g_support[(size_t)NNP * OUTF];
__device__ float g_resid[(size_t)NNP * OUTF];
__device__ __align__(16) __nv_bfloat16 g_whi[128 * 128];
__device__ __align__(16) __nv_bfloat16 g_wlo[128 * 128];
__device__ int  g_cnt[NNP + 1];             // [NNP] = overflow counter
__device__ int  g_ovf[MAX_OVF];
__device__ int2 g_ell[(size_t)NNP * CAP];   // {src*16 (float4 units), w bits}

// ---------------------------------------------------------------------------
// Kernel 1: ELL placement (blocks 0..PBLK-1, 2 edges/thread) + weight split
// prep (blocks PBLK..PBLK+WBLK-1). Both independent preludes; no smem.
// ---------------------------------------------------------------------------
__device__ __forceinline__ void place_one(int e, const int* __restrict__ src,
                                          const int* __restrict__ dst, float w) {
  int d = __ldg(dst + e);
  int s = __ldg(src + e);
  int pos = atomicAdd(&g_cnt[d], 1);
  if (pos < CAP) {
    g_ell[(size_t)d * CAP + pos] = make_int2(s * (OUTF / 4), __float_as_int(w));
  } else {
    int o = atomicAdd(&g_cnt[NNP], 1);
    if (o < MAX_OVF) g_ovf[o] = e;
  }
}

__global__ void __launch_bounds__(256) place_prep_kernel(
    const int* __restrict__ src, const int* __restrict__ dst,
    const float* __restrict__ ew,
    const float* __restrict__ w, const float* __restrict__ rw) {
  unsigned b = blockIdx.x;
  if (b < PBLK) {
    unsigned e0 = b * 512u + threadIdx.x;
    unsigned e1 = e0 + 256u;
    float w0 = (e0 < NE) ? __ldg(ew + e0) : 0.f;
    float w1 = (e1 < NE) ? __ldg(ew + e1) : 0.f;
    if (e0 < NE) place_one((int)e0, src, dst, w0);
    if (e1 < NE) place_one((int)e1, src, dst, w1);
  } else {
    int i = (int)(b - PBLK) * 256 + threadIdx.x;
    if (i >= 128 * 128) return;
    int k = i >> 7, f = i & 127;
    float v = (f < 64) ? w[k * 64 + f] : rw[(f - 64) * 128 + k];
    __nv_bfloat16 h = __float2bfloat16(v);
    g_whi[i] = h;
    g_wlo[i] = __float2bfloat16(v - __bfloat162float(h));
  }
}

// ---------------------------------------------------------------------------
// Kernel 2: WMMA split-bf16 combined GEMM (support | resid).
// 128 nodes/block, 512 threads = 16 warps (4 m-tiles x 4 n-tiles),
// each warp 2x2 fragments of 16x16, 3 passes (hh, hl, lh), K=128.
// ---------------------------------------------------------------------------
#define LDX 136
#define LDW 136
#define SM_XHI 0
#define SM_XLO (128 * LDX)
#define SM_WHI (2 * 128 * LDX)
#define SM_WLO (2 * 128 * LDX + 128 * LDW)
#define GEMM_SMEM ((2 * 128 * LDX + 2 * 128 * LDW) * 2)   // 139264 B

__global__ void __launch_bounds__(512) gemm_kernel(const float* __restrict__ x) {
  extern __shared__ __nv_bfloat16 sm[];
  __nv_bfloat16* xhi = sm + SM_XHI;
  __nv_bfloat16* xlo = sm + SM_XLO;
  __nv_bfloat16* whi = sm + SM_WHI;
  __nv_bfloat16* wlo = sm + SM_WLO;
  const int tid = threadIdx.x;
  const int n0 = blockIdx.x * TILE_M;

  // Stage pre-split weights (2048 uint4 per array)
  {
    const uint4* sh = (const uint4*)g_whi;
    const uint4* sl = (const uint4*)g_wlo;
#pragma unroll
    for (int rep = 0; rep < 4; rep++) {
      int i = tid + rep * 512;
      int r = i >> 4, c = i & 15;
      *(uint4*)(whi + r * LDW + c * 8) = sh[i];
      *(uint4*)(wlo + r * LDW + c * 8) = sl[i];
    }
  }
  // Stage x (128 nodes x 32 float4), split hi/lo on the fly
#pragma unroll
  for (int rep = 0; rep < 8; rep++) {
    int i = tid + rep * 512;                 // 4096 float4
    int node = i >> 5, c = i & 31;
    int gn = n0 + node;
    if (gn >= NN) gn = NN - 1;
    float4 v = *(const float4*)(x + (size_t)gn * INF_ + c * 4);
    __nv_bfloat16 h0 = __float2bfloat16(v.x), h1 = __float2bfloat16(v.y);
    __nv_bfloat16 h2 = __float2bfloat16(v.z), h3 = __float2bfloat16(v.w);
    __nv_bfloat16 l0 = __float2bfloat16(v.x - __bfloat162float(h0));
    __nv_bfloat16 l1 = __float2bfloat16(v.y - __bfloat162float(h1));
    __nv_bfloat16 l2 = __float2bfloat16(v.z - __bfloat162float(h2));
    __nv_bfloat16 l3 = __float2bfloat16(v.w - __bfloat162float(h3));
    __nv_bfloat162* ph = (__nv_bfloat162*)(xhi + node * LDX + c * 4);
    __nv_bfloat162* pl = (__nv_bfloat162*)(xlo + node * LDX + c * 4);
    ph[0] = __nv_bfloat162(h0, h1); ph[1] = __nv_bfloat162(h2, h3);
    pl[0] = __nv_bfloat162(l0, l1); pl[1] = __nv_bfloat162(l2, l3);
  }
  __syncthreads();

  const int wid = tid >> 5;
  const int wm = wid & 3;       // node 32-tile (0..3)
  const int wn = wid >> 2;      // feature 32-tile (0..3)

  wmma::fragment<wmma::accumulator, 16, 16, 16, float> acc[2][2];
#pragma unroll
  for (int i = 0; i < 2; i++)
#pragma unroll
    for (int j = 0; j < 2; j++) wmma::fill_fragment(acc[i][j], 0.f);

#pragma unroll
  for (int k = 0; k < 128; k += 16) {
    wmma::fragment<wmma::matrix_a, 16, 16, 16, __nv_bfloat16, wmma::row_major> ahi[2], alo[2];
    wmma::fragment<wmma::matrix_b, 16, 16, 16, __nv_bfloat16, wmma::row_major> bhi[2], blo[2];
#pragma unroll
    for (int i = 0; i < 2; i++) {
      wmma::load_matrix_sync(ahi[i], xhi + (wm * 32 + i * 16) * LDX + k, LDX);
      wmma::load_matrix_sync(alo[i], xlo + (wm * 32 + i * 16) * LDX + k, LDX);
    }
#pragma unroll
    for (int j = 0; j < 2; j++) {
      wmma::load_matrix_sync(bhi[j], whi + k * LDW + wn * 32 + j * 16, LDW);
      wmma::load_matrix_sync(blo[j], wlo + k * LDW + wn * 32 + j * 16, LDW);
    }
#pragma unroll
    for (int i = 0; i < 2; i++)
#pragma unroll
      for (int j = 0; j < 2; j++) {
        wmma::mma_sync(acc[i][j], ahi[i], bhi[j], acc[i][j]);
        wmma::mma_sync(acc[i][j], ahi[i], blo[j], acc[i][j]);
        wmma::mma_sync(acc[i][j], alo[i], bhi[j], acc[i][j]);
      }
  }

#pragma unroll
  for (int i = 0; i < 2; i++)
#pragma unroll
    for (int j = 0; j < 2; j++) {
      int row = n0 + wm * 32 + i * 16;       // < NNP (padded)
      int col = wn * 32 + j * 16;
      float* dstp = (col < 64)
                        ? (g_support + (size_t)row * OUTF + col)
                        : (g_resid + (size_t)row * OUTF + (col - 64));
      wmma::store_matrix_sync(dstp, acc[i][j], OUTF, wmma::mem_row_major);
    }
}

// ---------------------------------------------------------------------------
// Kernel 3: fused gather + finalize. 16 lanes/node (2 nodes per warp).
// Broadcast-LDG ELL entries, MLP=8 gathers, 32-bit address math.
// Padding entries carry w=0 bits -> no per-FMA predicate.
// Overflow nodes (deg>CAP) additionally scan the tiny g_ovf list.
// ---------------------------------------------------------------------------
__global__ void __launch_bounds__(256) gather_finalize(
    float* __restrict__ out, const float* __restrict__ bias,
    const float* __restrict__ gamma, const float* __restrict__ beta,
    const float* __restrict__ res_b,
    const int* __restrict__ src, const int* __restrict__ dst,
    const float* __restrict__ ew) {
  unsigned t = blockIdx.x * 256u + threadIdx.x;
  unsigned n = t >> 4;
  unsigned q = t & 15;
  const unsigned gmask = 0xffffu << (threadIdx.x & 16);

  int deg_raw = g_cnt[n];
  int deg = deg_raw > CAP ? CAP : deg_raw;

  float4 acc = make_float4(0.f, 0.f, 0.f, 0.f);
  const int2* ellrow = g_ell + (size_t)n * CAP;
  const float4* supf4 = (const float4*)g_support;

  for (int base = 0; base < deg; base += 8) {
    int2 e[8];
#pragma unroll
    for (int u = 0; u < 8; u++) {
      int idx = base + u;
      e[u] = (idx < deg) ? __ldg(ellrow + idx) : make_int2(0, 0);
    }
    float4 v[8];
#pragma unroll
    for (int u = 0; u < 8; u++)
      v[u] = __ldg(supf4 + (unsigned)(e[u].x + q));
#pragma unroll
    for (int u = 0; u < 8; u++) {
      float w = __int_as_float(e[u].y);    // 0 for padded entries
      acc.x = fmaf(w, v[u].x, acc.x);
      acc.y = fmaf(w, v[u].y, acc.y);
      acc.z = fmaf(w, v[u].z, acc.z);
      acc.w = fmaf(w, v[u].w, acc.w);
    }
  }

  if (deg_raw > CAP) {          // essentially never taken
    int m = g_cnt[NNP];
    if (m > MAX_OVF) m = MAX_OVF;
    for (int i = 0; i < m; i++) {
      int e = g_ovf[i];
      if ((unsigned)__ldg(dst + e) == n) {
        float w = __ldg(ew + e);
        float4 v = __ldg(supf4 + (unsigned)(__ldg(src + e) * (OUTF / 4) + q));
        acc.x = fmaf(w, v.x, acc.x); acc.y = fmaf(w, v.y, acc.y);
        acc.z = fmaf(w, v.z, acc.z); acc.w = fmaf(w, v.w, acc.w);
      }
    }
  }

  // finalize
  float4 b = *(const float4*)(bias + q * 4);
  acc.x += b.x; acc.y += b.y; acc.z += b.z; acc.w += b.w;

  float s  = acc.x + acc.y + acc.z + acc.w;
  float s2 = acc.x * acc.x + acc.y * acc.y + acc.z * acc.z + acc.w * acc.w;
#pragma unroll
  for (int m = 8; m >= 1; m >>= 1) {
    s  += __shfl_xor_sync(gmask, s, m, 16);
    s2 += __shfl_xor_sync(gmask, s2, m, 16);
  }
  float mu  = s * (1.f / 64.f);
  float var = s2 * (1.f / 64.f) - mu * mu;
  float inv = rsqrtf(var + 1e-5f);

  float4 g  = *(const float4*)(gamma + q * 4);
  float4 be = *(const float4*)(beta + q * 4);
  float4 r  = *(const float4*)(g_resid + (size_t)n * OUTF + q * 4);
  float4 rb = *(const float4*)(res_b + q * 4);

  acc.x = fmaxf((acc.x - mu) * inv * g.x + be.x, 0.f) + r.x + rb.x;
  acc.y = fmaxf((acc.y - mu) * inv * g.y + be.y, 0.f) + r.y + rb.y;
  acc.z = fmaxf((acc.z - mu) * inv * g.z + be.z, 0.f) + r.z + rb.z;
  acc.w = fmaxf((acc.w - mu) * inv * g.w + be.w, 0.f) + r.w + rb.w;

  *(float4*)(out + (size_t)n * OUTF + q * 4) = acc;
}

// ---------------------------------------------------------------------------
extern "C" void kernel_launch(void* const* d_in, const int* in_sizes, int n_in,
                              void* d_out, int out_size) {
  const float* x      = (const float*)d_in[0];
  const float* weight = (const float*)d_in[1];
  const float* bias   = (const float*)d_in[2];
  const float* gamma  = (const float*)d_in[3];
  const float* beta   = (const float*)d_in[4];
  const float* res_w  = (const float*)d_in[5];
  const float* res_b  = (const float*)d_in[6];
  const float* ew     = (const float*)d_in[7];
  const int*   esrc   = (const int*)d_in[8];
  const int*   edst   = (const int*)d_in[9];
  float* out = (float*)d_out;

  cudaFuncSetAttribute(gemm_kernel,
                       cudaFuncAttributeMaxDynamicSharedMemorySize, GEMM_SMEM);

  void* cntp = nullptr;
  cudaGetSymbolAddress(&cntp, g_cnt);
  cudaMemsetAsync(cntp, 0, (NNP + 1) * sizeof(int), 0);

  place_prep_kernel<<<PBLK + WBLK, 256>>>(esrc, edst, ew, weight, res_w);

  gemm_kernel<<<NBLK, 512, GEMM_SMEM>>>(x);

  gather_finalize<<<(NN * 16) / 256, 256>>>(out, bias, gamma, beta, res_b,
                                            esrc, edst, ew);
}

// round 14
// speedup vs baseline: 1.1684x; 1.0772x over previous
#include <cuda_runtime.h>
#include <cuda_bf16.h>
#include <cuda_fp16.h>
#include <mma.h>
using namespace nvcuda;

#define NN   100000
#define NNP  100096   // padded to 128-node tiles: 782*128
#define NE   1600000
#define INF_ 128
#define OUTF 64
#define TILE_M 128
#define NBLK ((NN + TILE_M - 1) / TILE_M)   // 782
#define CAP  64
#define MAX_OVF 65536
#define PBLK ((NE / 4 + 255) / 256)         // placement blocks (4 edges/thread)
#define WBLK 64                             // weight-prep blocks

__device__ __align__(16) __half g_support_h[(size_t)NNP * OUTF];  // fp16 support
__device__ float g_resid[(size_t)NNP * OUTF];
__device__ __align__(16) __nv_bfloat16 g_whi[128 * 128];
__device__ __align__(16) __nv_bfloat16 g_wlo[128 * 128];
__device__ int  g_cnt[NNP + 1];             // [NNP] = overflow counter
__device__ int  g_ovf[MAX_OVF];
__device__ int2 g_ell[(size_t)NNP * CAP];   // {src*16 (uint2 row units), w bits}

// ---------------------------------------------------------------------------
// Kernel 1: ELL placement (4 edges/thread, independent atomic chains) +
// weight split prep (last WBLK blocks). No smem; both streaming preludes.
// ---------------------------------------------------------------------------
__global__ void __launch_bounds__(256) place_prep_kernel(
    const int* __restrict__ src, const int* __restrict__ dst,
    const float* __restrict__ ew,
    const float* __restrict__ w, const float* __restrict__ rw) {
  unsigned b = blockIdx.x;
  if (b < PBLK) {
    unsigned base = b * 1024u + threadIdx.x;
    int dd[4], ss[4];
    float ww[4];
    bool ok[4];
#pragma unroll
    for (int u = 0; u < 4; u++) {
      unsigned e = base + u * 256u;
      ok[u] = e < NE;
      if (ok[u]) {
        dd[u] = __ldg(dst + e);
        ss[u] = __ldg(src + e);
        ww[u] = __ldg(ew + e);
      }
    }
    int pos[4];
#pragma unroll
    for (int u = 0; u < 4; u++)
      if (ok[u]) pos[u] = atomicAdd(&g_cnt[dd[u]], 1);
#pragma unroll
    for (int u = 0; u < 4; u++) {
      if (!ok[u]) continue;
      if (pos[u] < CAP) {
        g_ell[(size_t)dd[u] * CAP + pos[u]] =
            make_int2(ss[u] * (OUTF / 4), __float_as_int(ww[u]));
      } else {
        int o = atomicAdd(&g_cnt[NNP], 1);
        if (o < MAX_OVF) g_ovf[o] = (int)(base + u * 256u);
      }
    }
  } else {
    int i = (int)(b - PBLK) * 256 + threadIdx.x;
    if (i >= 128 * 128) return;
    int k = i >> 7, f = i & 127;
    float v = (f < 64) ? w[k * 64 + f] : rw[(f - 64) * 128 + k];
    __nv_bfloat16 h = __float2bfloat16(v);
    g_whi[i] = h;
    g_wlo[i] = __float2bfloat16(v - __bfloat162float(h));
  }
}

// ---------------------------------------------------------------------------
// Kernel 2: WMMA split-bf16 combined GEMM (support | resid).
// 128 nodes/block, 512 threads = 16 warps (4 m x 4 n), 3 passes, K=128.
// Support columns stored as fp16 via smem staging (x smem reused post-MMA).
// ---------------------------------------------------------------------------
#define LDX 136
#define LDW 136
#define SM_XHI 0
#define SM_XLO (128 * LDX)
#define SM_WHI (2 * 128 * LDX)
#define SM_WLO (2 * 128 * LDX + 128 * LDW)
#define GEMM_SMEM ((2 * 128 * LDX + 2 * 128 * LDW) * 2)   // 139264 B
#define LDS_ 72   // float staging stride (multiple of 8, 288B rows)

__global__ void __launch_bounds__(512) gemm_kernel(const float* __restrict__ x) {
  extern __shared__ __nv_bfloat16 sm[];
  __nv_bfloat16* xhi = sm + SM_XHI;
  __nv_bfloat16* xlo = sm + SM_XLO;
  __nv_bfloat16* whi = sm + SM_WHI;
  __nv_bfloat16* wlo = sm + SM_WLO;
  const int tid = threadIdx.x;
  const int n0 = blockIdx.x * TILE_M;

  // Stage pre-split weights (2048 uint4 per array)
  {
    const uint4* sh = (const uint4*)g_whi;
    const uint4* sl = (const uint4*)g_wlo;
#pragma unroll
    for (int rep = 0; rep < 4; rep++) {
      int i = tid + rep * 512;
      int r = i >> 4, c = i & 15;
      *(uint4*)(whi + r * LDW + c * 8) = sh[i];
      *(uint4*)(wlo + r * LDW + c * 8) = sl[i];
    }
  }
  // Stage x (128 nodes x 32 float4), split hi/lo on the fly
#pragma unroll
  for (int rep = 0; rep < 8; rep++) {
    int i = tid + rep * 512;                 // 4096 float4
    int node = i >> 5, c = i & 31;
    int gn = n0 + node;
    if (gn >= NN) gn = NN - 1;
    float4 v = *(const float4*)(x + (size_t)gn * INF_ + c * 4);
    __nv_bfloat16 h0 = __float2bfloat16(v.x), h1 = __float2bfloat16(v.y);
    __nv_bfloat16 h2 = __float2bfloat16(v.z), h3 = __float2bfloat16(v.w);
    __nv_bfloat16 l0 = __float2bfloat16(v.x - __bfloat162float(h0));
    __nv_bfloat16 l1 = __float2bfloat16(v.y - __bfloat162float(h1));
    __nv_bfloat16 l2 = __float2bfloat16(v.z - __bfloat162float(h2));
    __nv_bfloat16 l3 = __float2bfloat16(v.w - __bfloat162float(h3));
    __nv_bfloat162* ph = (__nv_bfloat162*)(xhi + node * LDX + c * 4);
    __nv_bfloat162* pl = (__nv_bfloat162*)(xlo + node * LDX + c * 4);
    ph[0] = __nv_bfloat162(h0, h1); ph[1] = __nv_bfloat162(h2, h3);
    pl[0] = __nv_bfloat162(l0, l1); pl[1] = __nv_bfloat162(l2, l3);
  }
  __syncthreads();

  const int wid = tid >> 5;
  const int wm = wid & 3;       // node 32-tile (0..3)
  const int wn = wid >> 2;      // feature 32-tile (0..3)

  wmma::fragment<wmma::accumulator, 16, 16, 16, float> acc[2][2];
#pragma unroll
  for (int i = 0; i < 2; i++)
#pragma unroll
    for (int j = 0; j < 2; j++) wmma::fill_fragment(acc[i][j], 0.f);

#pragma unroll
  for (int k = 0; k < 128; k += 16) {
    wmma::fragment<wmma::matrix_a, 16, 16, 16, __nv_bfloat16, wmma::row_major> ahi[2], alo[2];
    wmma::fragment<wmma::matrix_b, 16, 16, 16, __nv_bfloat16, wmma::row_major> bhi[2], blo[2];
#pragma unroll
    for (int i = 0; i < 2; i++) {
      wmma::load_matrix_sync(ahi[i], xhi + (wm * 32 + i * 16) * LDX + k, LDX);
      wmma::load_matrix_sync(alo[i], xlo + (wm * 32 + i * 16) * LDX + k, LDX);
    }
#pragma unroll
    for (int j = 0; j < 2; j++) {
      wmma::load_matrix_sync(bhi[j], whi + k * LDW + wn * 32 + j * 16, LDW);
      wmma::load_matrix_sync(blo[j], wlo + k * LDW + wn * 32 + j * 16, LDW);
    }
#pragma unroll
    for (int i = 0; i < 2; i++)
#pragma unroll
      for (int j = 0; j < 2; j++) {
        wmma::mma_sync(acc[i][j], ahi[i], bhi[j], acc[i][j]);
        wmma::mma_sync(acc[i][j], ahi[i], blo[j], acc[i][j]);
        wmma::mma_sync(acc[i][j], alo[i], bhi[j], acc[i][j]);
      }
  }

  __syncthreads();   // x smem no longer needed; reuse as fp32 staging
  float* stage = (float*)sm;   // [128][LDS_]

#pragma unroll
  for (int i = 0; i < 2; i++)
#pragma unroll
    for (int j = 0; j < 2; j++) {
      int rloc = wm * 32 + i * 16;
      int col = wn * 32 + j * 16;
      if (col < 64) {
        wmma::store_matrix_sync(stage + rloc * LDS_ + col, acc[i][j], LDS_,
                                wmma::mem_row_major);
      } else {
        wmma::store_matrix_sync(g_resid + (size_t)(n0 + rloc) * OUTF + (col - 64),
                                acc[i][j], OUTF, wmma::mem_row_major);
      }
    }
  __syncthreads();

  // Convert staged support to fp16: 2048 uint2 writes (4 halves each)
  uint2* suph = (uint2*)g_support_h;
#pragma unroll
  for (int rep = 0; rep < 4; rep++) {
    int i = tid + rep * 512;        // 0..2047
    int r = i >> 4, c = i & 15;
    float4 v = *(const float4*)(stage + r * LDS_ + c * 4);
    __half2 h01 = __floats2half2_rn(v.x, v.y);
    __half2 h23 = __floats2half2_rn(v.z, v.w);
    uint2 o;
    o.x = *(unsigned*)&h01;
    o.y = *(unsigned*)&h23;
    suph[(size_t)(n0 + r) * 16 + c] = o;
  }
}

// ---------------------------------------------------------------------------
// Kernel 3: fused gather + finalize. 16 lanes/node, fp16 support rows
// (uint2 = 4 halves per lane -> 128B/edge), MLP=8, broadcast-LDG ELL.
// ---------------------------------------------------------------------------
__global__ void __launch_bounds__(256) gather_finalize(
    float* __restrict__ out, const float* __restrict__ bias,
    const float* __restrict__ gamma, const float* __restrict__ beta,
    const float* __restrict__ res_b,
    const int* __restrict__ src, const int* __restrict__ dst,
    const float* __restrict__ ew) {
  unsigned t = blockIdx.x * 256u + threadIdx.x;
  unsigned n = t >> 4;
  unsigned q = t & 15;
  const unsigned gmask = 0xffffu << (threadIdx.x & 16);

  int deg_raw = g_cnt[n];
  int deg = deg_raw > CAP ? CAP : deg_raw;

  float4 acc = make_float4(0.f, 0.f, 0.f, 0.f);
  const int2* ellrow = g_ell + (size_t)n * CAP;
  const uint2* suph = (const uint2*)g_support_h;

  for (int base = 0; base < deg; base += 8) {
    int2 e[8];
#pragma unroll
    for (int u = 0; u < 8; u++) {
      int idx = base + u;
      e[u] = (idx < deg) ? __ldg(ellrow + idx) : make_int2(0, 0);
    }
    uint2 raw[8];
#pragma unroll
    for (int u = 0; u < 8; u++)
      raw[u] = __ldg(suph + (unsigned)(e[u].x + q));
#pragma unroll
    for (int u = 0; u < 8; u++) {
      float w = __int_as_float(e[u].y);    // 0 for padded entries
      float2 v01 = __half22float2(*(const __half2*)&raw[u].x);
      float2 v23 = __half22float2(*(const __half2*)&raw[u].y);
      acc.x = fmaf(w, v01.x, acc.x);
      acc.y = fmaf(w, v01.y, acc.y);
      acc.z = fmaf(w, v23.x, acc.z);
      acc.w = fmaf(w, v23.y, acc.w);
    }
  }

  if (deg_raw > CAP) {          // essentially never taken
    int m = g_cnt[NNP];
    if (m > MAX_OVF) m = MAX_OVF;
    for (int i = 0; i < m; i++) {
      int e = g_ovf[i];
      if ((unsigned)__ldg(dst + e) == n) {
        float w = __ldg(ew + e);
        uint2 raw = __ldg(suph + (unsigned)(__ldg(src + e) * (OUTF / 4) + q));
        float2 v01 = __half22float2(*(const __half2*)&raw.x);
        float2 v23 = __half22float2(*(const __half2*)&raw.y);
        acc.x = fmaf(w, v01.x, acc.x); acc.y = fmaf(w, v01.y, acc.y);
        acc.z = fmaf(w, v23.x, acc.z); acc.w = fmaf(w, v23.y, acc.w);
      }
    }
  }

  // finalize
  float4 b = *(const float4*)(bias + q * 4);
  acc.x += b.x; acc.y += b.y; acc.z += b.z; acc.w += b.w;

  float s  = acc.x + acc.y + acc.z + acc.w;
  float s2 = acc.x * acc.x + acc.y * acc.y + acc.z * acc.z + acc.w * acc.w;
#pragma unroll
  for (int m = 8; m >= 1; m >>= 1) {
    s  += __shfl_xor_sync(gmask, s, m, 16);
    s2 += __shfl_xor_sync(gmask, s2, m, 16);
  }
  float mu  = s * (1.f / 64.f);
  float var = s2 * (1.f / 64.f) - mu * mu;
  float inv = rsqrtf(var + 1e-5f);

  float4 g  = *(const float4*)(gamma + q * 4);
  float4 be = *(const float4*)(beta + q * 4);
  float4 r  = *(const float4*)(g_resid + (size_t)n * OUTF + q * 4);
  float4 rb = *(const float4*)(res_b + q * 4);

  acc.x = fmaxf((acc.x - mu) * inv * g.x + be.x, 0.f) + r.x + rb.x;
  acc.y = fmaxf((acc.y - mu) * inv * g.y + be.y, 0.f) + r.y + rb.y;
  acc.z = fmaxf((acc.z - mu) * inv * g.z + be.z, 0.f) + r.z + rb.z;
  acc.w = fmaxf((acc.w - mu) * inv * g.w + be.w, 0.f) + r.w + rb.w;

  *(float4*)(out + (size_t)n * OUTF + q * 4) = acc;
}

// ---------------------------------------------------------------------------
extern "C" void kernel_launch(void* const* d_in, const int* in_sizes, int n_in,
                              void* d_out, int out_size) {
  const float* x      = (const float*)d_in[0];
  const float* weight = (const float*)d_in[1];
  const float* bias   = (const float*)d_in[2];
  const float* gamma  = (const float*)d_in[3];
  const float* beta   = (const float*)d_in[4];
  const float* res_w  = (const float*)d_in[5];
  const float* res_b  = (const float*)d_in[6];
  const float* ew     = (const float*)d_in[7];
  const int*   esrc   = (const int*)d_in[8];
  const int*   edst   = (const int*)d_in[9];
  float* out = (float*)d_out;

  cudaFuncSetAttribute(gemm_kernel,
                       cudaFuncAttributeMaxDynamicSharedMemorySize, GEMM_SMEM);

  void* cntp = nullptr;
  cudaGetSymbolAddress(&cntp, g_cnt);
  cudaMemsetAsync(cntp, 0, (NNP + 1) * sizeof(int), 0);

  place_prep_kernel<<<PBLK + WBLK, 256>>>(esrc, edst, ew, weight, res_w);

  gemm_kernel<<<NBLK, 512, GEMM_SMEM>>>(x);

  gather_finalize<<<(NN * 16) / 256, 256>>>(out, bias, gamma, beta, res_b,
                                            esrc, edst, ew);
}